// round 15
// baseline (speedup 1.0000x reference)
#include <cuda_runtime.h>
#include <cstdint>

// out[b,k,oc,x] = sum_ci W[k,oc,ci]*in[b,ci,k,x] + bias[k,oc]
// in: [4096,128,9,9]  w: [9,128,128]  bias: [9,128]  out: [4096,9,128,9] (f32)
//
// R15 = R14 core (4Mx3N warps, 32x24 warp tile, packed-A g_W2, 6-stage ring)
// with the producer rebuilt on 16B cp.async:
//   row word-addr w has pad = w&3 = (ci+k)&3; copy aligned window [w-pad, w-pad+12)
//   as 3 x 16B cp.async into 12-word smem slots; consumer adds per-lane pad=(tl+k)&3.
// 3x fewer LSU ops (2304 -> 768 per CTA-quarter), overfetch 1.78x -> 1.33x.

#define KK     9
#define CIN    128
#define COUT   128
#define NB     8
#define TILES  4
#define NTHR   384
#define NBUF   6
#define NSTEP  (4 * TILES)      // 16 quarters per CTA

#define SCI   104               // words per ci row (8 bl * 12 + 8 pad); 104%32=8
#define XQ_WORDS (32 * SCI)     // 3328 words per stage (13312 B)
#define SMEM_BYTES (NBUF * XQ_WORDS * 4)   // 79872 -> 2 CTAs/SM

// packed A-frags: [k][wm(4)][ks(16)][mf(2)][lane(32)][4] tf32 bits
#define W2_WORDS (KK * 4 * 16 * 2 * 32 * 4)   // 147456
__device__ uint32_t g_W2[W2_WORDS];

__device__ __forceinline__ uint32_t f2tf32(float f) {
    uint32_t u;
    asm("cvt.rna.tf32.f32 %0, %1;" : "=r"(u) : "f"(f));
    return u;
}
__device__ __forceinline__ uint32_t smem_u32(const void* p) {
    uint32_t a;
    asm("{ .reg .u64 t; cvta.to.shared.u64 t, %1; cvt.u32.u64 %0, t; }" : "=r"(a) : "l"(p));
    return a;
}
__device__ __forceinline__ void cp16(uint32_t dst, const float* src) {
    asm volatile("cp.async.ca.shared.global [%0], [%1], 16;" :: "r"(dst), "l"(src));
}
__device__ __forceinline__ void mma_tf32(float* d, const uint32_t* a, const uint32_t* b) {
    asm volatile(
        "mma.sync.aligned.m16n8k8.row.col.f32.tf32.tf32.f32 "
        "{%0,%1,%2,%3}, {%4,%5,%6,%7}, {%8,%9}, {%0,%1,%2,%3};"
        : "+f"(d[0]), "+f"(d[1]), "+f"(d[2]), "+f"(d[3])
        : "r"(a[0]), "r"(a[1]), "r"(a[2]), "r"(a[3]), "r"(b[0]), "r"(b[1]));
}

// ---- prep: w[9][128][128] f32 -> g_W2 packed tf32 A-frags ----
__global__ void prep_w_kernel(const float* __restrict__ w) {
    int idx = blockIdx.x * 256 + threadIdx.x;
    if (idx >= W2_WORDS) return;
    int j    = idx & 3;
    int lane = (idx >> 2) & 31;
    int mf   = (idx >> 7) & 1;
    int ks   = (idx >> 8) & 15;
    int wm   = (idx >> 12) & 3;
    int k    = idx >> 14;
    int g = lane >> 2, tl = lane & 3;
    int oc = wm * 32 + mf * 16 + g + (j & 1) * 8;
    int ci = ks * 8 + tl + ((j >> 1) & 1) * 4;
    g_W2[idx] = f2tf32(w[(k * COUT + oc) * CIN + ci]);
}

__global__ void __launch_bounds__(NTHR, 2)
gather_vertical_r15(const float* __restrict__ in,
                    const float* __restrict__ bias,
                    float* __restrict__ out)
{
    extern __shared__ uint32_t sX[];   // NBUF stages: [ci_l(32)][SCI]; row = 8 bl x 12-word windows

    const int tid = threadIdx.x;
    const int k   = blockIdx.x;
    const int yid = blockIdx.y;
    const int bbase = yid * TILES * NB;

    const uint32_t sx_base = smem_u32(sX);

    // ---- producer constants (threads 0..255: one row (bl, ci_l) each) ----
    const int pbl = (tid >> 5) & 7;            // 0..7
    const int pci = tid & 31;                  // 0..31
    const int ppad = (pci + k) & 3;            // row pad
    const bool prod = (tid < 256);
    // per stage s: w = ((bbase + t*NB + pbl)*128 + qi*32 + pci)*81 + 9k ; wa = w - ppad
    const uint32_t pdst_off = (pci * SCI + pbl * 12) * 4;    // byte offset within stage

    // ---- prologue: stages 0..NBUF-2 ----
    #pragma unroll
    for (int s = 0; s < NBUF - 1; s++) {
        if (prod) {
            const int tn = s >> 2, qn = s & 3;
            size_t w = ((size_t)(bbase + tn * NB + pbl) * CIN + qn * 32 + pci) * 81 + 9 * k;
            const float* sp = in + (w - ppad);
            uint32_t db = sx_base + s * (XQ_WORDS * 4) + pdst_off;
            cp16(db,      sp);
            cp16(db + 16, sp + 4);
            cp16(db + 32, sp + 8);
        }
        asm volatile("cp.async.commit_group;" ::: "memory");
    }

    // ---- consumer identity: 12 warps = 4(M) x 3(N) ----
    const int wid  = tid >> 5, lane = tid & 31;
    const int g    = lane >> 2, tl = lane & 3;
    const int wm   = wid & 3;          // oc base wm*32
    const int wn   = wid >> 2;         // n  base wn*24
    const int n0   = wn * 24;
    const int rA   = wm * 32 + g;
    const int cpad = (tl + k) & 3;     // per-lane pad for B reads
    float bv[4];
    #pragma unroll
    for (int m = 0; m < 4; m++) bv[m] = bias[k * COUT + rA + m * 8];

    // per-nt smem n-offsets (constant per thread): slot = (n/9)*12 + n%9 + pad
    int noff[3];
    #pragma unroll
    for (int nt = 0; nt < 3; nt++) {
        int n = n0 + nt * 8 + g;
        noff[nt] = (n / 9) * 12 + (n % 9) + cpad;
    }

    // packed A base: uint4 layout [k][wm][ks][mf][lane], 1024 uint4 per (k,wm)
    const uint4* wpbase = reinterpret_cast<const uint4*>(g_W2)
                          + (size_t)(k * 4 + wm) * 1024 + lane;

    float d[2][3][4];

    for (int s = 0; s < NSTEP; s++) {
        const int bi = s % NBUF;
        const int qi = s & 3;

        if (qi == 0) {
            #pragma unroll
            for (int mf = 0; mf < 2; mf++)
                #pragma unroll
                for (int nt = 0; nt < 3; nt++)
                    #pragma unroll
                    for (int j = 0; j < 4; j++) d[mf][nt][j] = 0.0f;
        }

        asm volatile("cp.async.wait_group %0;" :: "n"(NBUF - 2) : "memory");
        __syncthreads();

        // issue stage s+NBUF-1 into buffer (s-1)%NBUF (freed by the sync above)
        {
            const int sn = s + NBUF - 1;
            if (sn < NSTEP && prod) {
                const int tn = sn >> 2, qn = sn & 3, bn = sn % NBUF;
                size_t w = ((size_t)(bbase + tn * NB + pbl) * CIN + qn * 32 + pci) * 81 + 9 * k;
                const float* sp = in + (w - ppad);
                uint32_t db = sx_base + bn * (XQ_WORDS * 4) + pdst_off;
                cp16(db,      sp);
                cp16(db + 16, sp + 4);
                cp16(db + 32, sp + 8);
            }
            asm volatile("cp.async.commit_group;" ::: "memory");
        }

        // ---- MMA on buffer bi: 4 k-steps; per kstep: 2 LDG.128 A, 6 LDS B, 6 HMMA ----
        {
            const uint32_t* sb = sX + bi * XQ_WORDS + tl * SCI;
            #pragma unroll
            for (int kk2 = 0; kk2 < 4; kk2++) {
                const int ks = qi * 4 + kk2;
                uint4 av0 = wpbase[ks * 64];
                uint4 av1 = wpbase[ks * 64 + 32];
                uint32_t a0[4] = {av0.x, av0.y, av0.z, av0.w};
                uint32_t a1[4] = {av1.x, av1.y, av1.z, av1.w};

                const uint32_t* p0 = sb + kk2 * 8 * SCI;   // ci_l = kk2*8 + tl
                uint32_t b[3][2];
                #pragma unroll
                for (int nt = 0; nt < 3; nt++) {
                    b[nt][0] = p0[noff[nt]];
                    b[nt][1] = p0[4 * SCI + noff[nt]];
                }
                #pragma unroll
                for (int nt = 0; nt < 3; nt++) {
                    mma_tf32(d[0][nt], a0, b[nt]);
                    mma_tf32(d[1][nt], a1, b[nt]);
                }
            }
        }

        // ---- tile boundary: epilogue (direct STG) ----
        if (qi == 3) {
            const int t = s >> 2;
            float* ob = out + ((size_t)(bbase + t * NB) * 9 + k) * 1152;
            #pragma unroll
            for (int mf = 0; mf < 2; mf++) {
                int ra = rA + mf * 16, rb = ra + 8;
                float bva = bv[mf * 2], bvb = bv[mf * 2 + 1];
                #pragma unroll
                for (int nt = 0; nt < 3; nt++) {
                    int n   = n0 + nt * 8 + 2 * tl;
                    int b0q = n / 9,       x0 = n - 9 * b0q;
                    int b1q = (n + 1) / 9, x1 = (n + 1) - 9 * b1q;
                    float* c0 = ob + (size_t)b0q * 10368;
                    float* c1 = ob + (size_t)b1q * 10368;
                    c0[ra * 9 + x0] = d[mf][nt][0] + bva;
                    c1[ra * 9 + x1] = d[mf][nt][1] + bva;
                    c0[rb * 9 + x0] = d[mf][nt][2] + bvb;
                    c1[rb * 9 + x1] = d[mf][nt][3] + bvb;
                }
            }
        }
    }
}

extern "C" void kernel_launch(void* const* d_in, const int* in_sizes, int n_in,
                              void* d_out, int out_size)
{
    const float* in   = (const float*)d_in[0];
    const float* w    = (const float*)d_in[1];
    const float* bias = (const float*)d_in[2];
    float* out        = (float*)d_out;

    int B = in_sizes[0] / (CIN * 81);        // 4096

    prep_w_kernel<<<(W2_WORDS + 255) / 256, 256>>>(w);

    cudaFuncSetAttribute(gather_vertical_r15,
                         cudaFuncAttributeMaxDynamicSharedMemorySize, SMEM_BYTES);

    dim3 grid(KK, B / (NB * TILES));         // (9, 128)
    gather_vertical_r15<<<grid, NTHR, SMEM_BYTES>>>(in, bias, out);
}

// round 16
// speedup vs baseline: 1.2731x; 1.2731x over previous
#include <cuda_runtime.h>
#include <cstdint>

// out[b,k,oc,x] = sum_ci W[k,oc,ci]*in[b,ci,k,x] + bias[k,oc]
// in: [4096,128,9,9]  w: [9,128,128]  bias: [9,128]  out: [4096,9,128,9] (f32)
//
// R16 = R12 (4Mx3N warps, warp tile 32oc x 24n, packed-A g_W2, 4-stage cp.async ring)
// + smem-staged deferred epilogue:
//   qi==3: frags(+bias) -> sD[128][73] (STS, one-time)
//   next tile's qi==0 (after its syncthreads): coalesced sD -> gmem copy, overlapping MMA.

#define KK     9
#define CIN    128
#define COUT   128
#define NB     8
#define TILES  4
#define NTHR   384
#define NBUF   4
#define NSTEP  (NBUF * TILES)   // 16 quarters per CTA

#define SXS 72                  // stage stride: B-frag banks perfect
#define XQ_WORDS (32 * SXS)     // 2304 words per stage (9216 B)
#define SDS 73                  // sD stride: copy-read banks (9g mod 32) distinct
#define SD_WORDS (128 * SDS)    // 9344 words (37376 B)
#define RING_WORDS (NBUF * XQ_WORDS)       // 9216
#define SMEM_BYTES ((RING_WORDS + SD_WORDS) * 4)   // 74240 -> 2 CTAs/SM

// packed A-frags: [k][wm(4)][ks(16)][mf(2)][lane(32)][4] tf32 bits
#define W2_WORDS (KK * 4 * 16 * 2 * 32 * 4)   // 147456
__device__ uint32_t g_W2[W2_WORDS];

__device__ __forceinline__ uint32_t f2tf32(float f) {
    uint32_t u;
    asm("cvt.rna.tf32.f32 %0, %1;" : "=r"(u) : "f"(f));
    return u;
}
__device__ __forceinline__ uint32_t smem_u32(const void* p) {
    uint32_t a;
    asm("{ .reg .u64 t; cvta.to.shared.u64 t, %1; cvt.u32.u64 %0, t; }" : "=r"(a) : "l"(p));
    return a;
}
__device__ __forceinline__ void cp4(uint32_t dst, const float* src) {
    asm volatile("cp.async.ca.shared.global [%0], [%1], 4;" :: "r"(dst), "l"(src));
}
__device__ __forceinline__ void mma_tf32(float* d, const uint32_t* a, const uint32_t* b) {
    asm volatile(
        "mma.sync.aligned.m16n8k8.row.col.f32.tf32.tf32.f32 "
        "{%0,%1,%2,%3}, {%4,%5,%6,%7}, {%8,%9}, {%0,%1,%2,%3};"
        : "+f"(d[0]), "+f"(d[1]), "+f"(d[2]), "+f"(d[3])
        : "r"(a[0]), "r"(a[1]), "r"(a[2]), "r"(a[3]), "r"(b[0]), "r"(b[1]));
}

// ---- prep: w[9][128][128] f32 -> g_W2 packed tf32 A-frags ----
__global__ void prep_w_kernel(const float* __restrict__ w) {
    int idx = blockIdx.x * 256 + threadIdx.x;
    if (idx >= W2_WORDS) return;
    int j    = idx & 3;
    int lane = (idx >> 2) & 31;
    int mf   = (idx >> 7) & 1;
    int ks   = (idx >> 8) & 15;
    int wm   = (idx >> 12) & 3;
    int k    = idx >> 14;
    int g = lane >> 2, tl = lane & 3;
    int oc = wm * 32 + mf * 16 + g + (j & 1) * 8;
    int ci = ks * 8 + tl + ((j >> 1) & 1) * 4;
    g_W2[idx] = f2tf32(w[(k * COUT + oc) * CIN + ci]);
}

__global__ void __launch_bounds__(NTHR, 2)
gather_vertical_r16(const float* __restrict__ in,
                    const float* __restrict__ bias,
                    float* __restrict__ out)
{
    extern __shared__ uint32_t smem[];
    uint32_t* sX = smem;                        // 4 stages [32 ci][72 n]
    float*    sD = reinterpret_cast<float*>(smem + RING_WORDS);   // [128][73]

    const int tid = threadIdx.x;
    const int k   = blockIdx.x;
    const int yid = blockIdx.y;
    const int bbase = yid * TILES * NB;

    // ---- per-thread cp.async offsets (6 words per stage), loop-invariant ----
    const float* src = in + (size_t)bbase * (CIN * 81) + (size_t)k * 9;
    const uint32_t sx_base = smem_u32(sX);
    int goff[6], soff[6];
    #pragma unroll
    for (int j = 0; j < 6; j++) {
        int e  = tid + NTHR * j;      // 0..2303
        int q  = e / 9;               // bl*32 + ci_local
        int x  = e - 9 * q;
        int bl = q >> 5;
        int ci = q & 31;
        goff[j] = (bl * CIN + ci) * 81 + x;
        soff[j] = (ci * SXS + bl * 9 + x) * 4;
    }

    // ---- prologue: stages 0..2 ----
    #pragma unroll
    for (int s = 0; s < 3; s++) {
        const float* st = src + s * 32 * 81;
        const uint32_t db = sx_base + s * (XQ_WORDS * 4);
        #pragma unroll
        for (int j = 0; j < 6; j++) cp4(db + soff[j], st + goff[j]);
        asm volatile("cp.async.commit_group;" ::: "memory");
    }

    // ---- consumer identity: 12 warps = 4(M) x 3(N) ----
    const int wid  = tid >> 5, lane = tid & 31;
    const int g    = lane >> 2, tl = lane & 3;
    const int wm   = wid & 3;          // oc base wm*32
    const int wn   = wid >> 2;         // n  base wn*24
    const int n0   = wn * 24;
    const int rA   = wm * 32 + g;
    float bv[4];
    #pragma unroll
    for (int m = 0; m < 4; m++) bv[m] = bias[k * COUT + rA + m * 8];

    // packed A base: uint4 layout [k][wm][ks][mf][lane], 1024 uint4 per (k,wm)
    const uint4* wpbase = reinterpret_cast<const uint4*>(g_W2)
                          + (size_t)(k * 4 + wm) * 1024 + lane;

    const size_t out_tile_stride = (size_t)NB * 9 * 1152;   // per-tile out advance
    float* obase = out + ((size_t)bbase * 9 + k) * 1152;

    float d[2][3][4];

    for (int s = 0; s < NSTEP; s++) {
        const int qi = s & 3;

        if (qi == 0) {
            #pragma unroll
            for (int mf = 0; mf < 2; mf++)
                #pragma unroll
                for (int nt = 0; nt < 3; nt++)
                    #pragma unroll
                    for (int j = 0; j < 4; j++) d[mf][nt][j] = 0.0f;
        }

        asm volatile("cp.async.wait_group 2;" ::: "memory");   // stage s arrived
        __syncthreads();                                        // also publishes sD writes

        // issue stage s+3 into buffer (s+3)&3 (freed by the sync above)
        if (s + 3 < NSTEP) {
            const int sn = s + 3, tn = sn >> 2, qn = sn & 3;
            const float* st = src + (size_t)(tn * NB) * (CIN * 81) + qn * 32 * 81;
            const uint32_t db = sx_base + qn * (XQ_WORDS * 4);
            #pragma unroll
            for (int j = 0; j < 6; j++) cp4(db + soff[j], st + goff[j]);
        }
        asm volatile("cp.async.commit_group;" ::: "memory");

        // ---- deferred epilogue copy for the PREVIOUS tile (overlaps this tile's MMA) ----
        if (qi == 0 && s >= 4) {
            const int tp = (s >> 2) - 1;
            float* ob = obase + (size_t)tp * out_tile_stride;
            #pragma unroll
            for (int i = tid, it = 0; it < 24; i += NTHR, it++) {
                int bl = i / 1152;
                int r  = i - bl * 1152;       // r = oc*9 + x
                int oc = r / 9;
                int x  = r - 9 * oc;
                ob[(size_t)bl * 10368 + r] = sD[oc * SDS + bl * 9 + x];
            }
        }

        // ---- MMA on stage qi: 4 k-steps; per kstep: 2 LDG.128 A, 6 LDS B, 6 HMMA ----
        {
            const uint32_t* pb = sX + qi * XQ_WORDS + tl * SXS + g + n0;
            #pragma unroll
            for (int kk2 = 0; kk2 < 4; kk2++) {
                const int ks = qi * 4 + kk2;
                uint4 av0 = wpbase[ks * 64];          // mf0
                uint4 av1 = wpbase[ks * 64 + 32];     // mf1
                uint32_t a0[4] = {av0.x, av0.y, av0.z, av0.w};
                uint32_t a1[4] = {av1.x, av1.y, av1.z, av1.w};

                uint32_t b[3][2];
                #pragma unroll
                for (int nt = 0; nt < 3; nt++) {
                    b[nt][0] = pb[nt * 8];
                    b[nt][1] = pb[4 * SXS + nt * 8];
                }
                #pragma unroll
                for (int nt = 0; nt < 3; nt++) {
                    mma_tf32(d[0][nt], a0, b[nt]);
                    mma_tf32(d[1][nt], a1, b[nt]);
                }
                pb += 8 * SXS;
            }
        }

        // ---- tile boundary: stage frags(+bias) into sD ----
        if (qi == 3) {
            #pragma unroll
            for (int mf = 0; mf < 2; mf++) {
                int ra = rA + mf * 16, rb = ra + 8;
                float bva = bv[mf * 2], bvb = bv[mf * 2 + 1];
                #pragma unroll
                for (int nt = 0; nt < 3; nt++) {
                    int n = n0 + nt * 8 + 2 * tl;
                    sD[ra * SDS + n]     = d[mf][nt][0] + bva;
                    sD[ra * SDS + n + 1] = d[mf][nt][1] + bva;
                    sD[rb * SDS + n]     = d[mf][nt][2] + bvb;
                    sD[rb * SDS + n + 1] = d[mf][nt][3] + bvb;
                }
            }
        }
    }

    // ---- flush last tile ----
    __syncthreads();
    {
        float* ob = obase + (size_t)(TILES - 1) * out_tile_stride;
        #pragma unroll
        for (int i = tid, it = 0; it < 24; i += NTHR, it++) {
            int bl = i / 1152;
            int r  = i - bl * 1152;
            int oc = r / 9;
            int x  = r - 9 * oc;
            ob[(size_t)bl * 10368 + r] = sD[oc * SDS + bl * 9 + x];
        }
    }
}

extern "C" void kernel_launch(void* const* d_in, const int* in_sizes, int n_in,
                              void* d_out, int out_size)
{
    const float* in   = (const float*)d_in[0];
    const float* w    = (const float*)d_in[1];
    const float* bias = (const float*)d_in[2];
    float* out        = (float*)d_out;

    int B = in_sizes[0] / (CIN * 81);        // 4096

    prep_w_kernel<<<(W2_WORDS + 255) / 256, 256>>>(w);

    cudaFuncSetAttribute(gather_vertical_r16,
                         cudaFuncAttributeMaxDynamicSharedMemorySize, SMEM_BYTES);

    dim3 grid(KK, B / (NB * TILES));         // (9, 128)
    gather_vertical_r16<<<grid, NTHR, SMEM_BYTES>>>(in, bias, out);
}